// round 8
// baseline (speedup 1.0000x reference)
#include <cuda_runtime.h>
#include <mma.h>
#include <cstdint>
#include <math.h>

using namespace nvcuda;

// ---------------- problem constants ----------------
#define BATCH 64
#define NC 1024
#define NT 1024
#define H 512
#define NP (BATCH*(NC+NT))   // 131072 points
#define NCTX (BATCH*NC)      // 65536 context rows
#define NRP1 513
#define LD 520
#define COVSTRIDE (NRP1*LD)
#define OMEGA0 30.0f

// ---------------- scratch (static device globals; referenced ONLY in device code) ----------------
__device__ float g_bufA[(size_t)NP * H];
__device__ float g_bufB[(size_t)NP * H];
__device__ float g_feat[(size_t)NP * H];
__device__ float g_cov[(size_t)BATCH * COVSTRIDE];
__device__ float g_xty[BATCH * LD];
__device__ float g_yc[BATCH * NC];
__device__ float g_mean[BATCH];
__device__ float g_std[BATCH];

// ---------------- helpers ----------------
__device__ __forceinline__ uint32_t smem_u32(const void* p) {
    uint32_t a;
    asm("{ .reg .u64 t; cvta.to.shared.u64 t, %1; cvt.u32.u64 %0, t; }" : "=r"(a) : "l"(p));
    return a;
}
__device__ __forceinline__ void cp16(uint32_t dst, const void* src) {
    asm volatile("cp.async.cg.shared.global [%0], [%1], 16;" :: "r"(dst), "l"(src));
}
#define CP_COMMIT() asm volatile("cp.async.commit_group;" ::: "memory")
#define CP_WAIT1()  asm volatile("cp.async.wait_group 1;" ::: "memory")
#define CP_WAIT0()  asm volatile("cp.async.wait_group 0;" ::: "memory")

__device__ __forceinline__ float tf32r(float v) {
    uint32_t u;
    asm("cvt.rna.tf32.f32 %0, %1;" : "=r"(u) : "f"(v));
    return __uint_as_float(u);
}

// ---------------- 1) per-batch mean/std (ddof=1) + normalize ----------------
__global__ void __launch_bounds__(256) stats_kernel(const float* __restrict__ y) {
    const int b = blockIdx.x, tid = threadIdx.x;
    __shared__ float red[256];
    float v[4];
#pragma unroll
    for (int t = 0; t < 4; t++) v[t] = y[b * NC + tid + t * 256];
    red[tid] = v[0] + v[1] + v[2] + v[3]; __syncthreads();
    for (int st = 128; st > 0; st >>= 1) { if (tid < st) red[tid] += red[tid + st]; __syncthreads(); }
    const float mean = red[0] * (1.0f / NC);
    __syncthreads();
    float q = 0.f;
#pragma unroll
    for (int t = 0; t < 4; t++) { float d = v[t] - mean; q += d * d; }
    red[tid] = q; __syncthreads();
    for (int st = 128; st > 0; st >>= 1) { if (tid < st) red[tid] += red[tid + st]; __syncthreads(); }
    const float sd = sqrtf(red[0] * (1.0f / (NC - 1)));
    const float inv = 1.0f / sd;
#pragma unroll
    for (int t = 0; t < 4; t++) g_yc[b * NC + tid + t * 256] = (v[t] - mean) * inv;
    if (tid == 0) { g_mean[b] = mean; g_std[b] = sd; }
}

// ---------------- 2) SIREN layer 0 (XD=1, elementwise) ----------------
__global__ void __launch_bounds__(256) layer0_kernel(const float* __restrict__ xc,
                                                     const float* __restrict__ xt,
                                                     const float* __restrict__ W0,
                                                     const float* __restrict__ b0) {
    const int idx = blockIdx.x * 256 + threadIdx.x;
    const int p = idx >> 7;
    const int j4 = (idx & 127) << 2;
    const float x = (p < NCTX) ? xc[p] : xt[p - NCTX];
    const float4 w = *(const float4*)(W0 + j4);
    const float4 bb = *(const float4*)(b0 + j4);
    float4 o;
    o.x = sinf(OMEGA0 * fmaf(x, w.x, bb.x));
    o.y = sinf(OMEGA0 * fmaf(x, w.y, bb.y));
    o.z = sinf(OMEGA0 * fmaf(x, w.z, bb.z));
    o.w = sinf(OMEGA0 * fmaf(x, w.w, bb.w));
    *(float4*)(g_bufA + (size_t)p * H + j4) = o;
}

// ---------------- 3) wmma tf32 3-term GEMM: C = act(A @ W + b) ----------------
// SEL 0: g_bufA -> g_bufB (sin). SEL 1: g_bufB -> g_bufA (sin). SEL 2: g_bufA -> g_feat (linear).
// CTA 128x128, 8 warps (64x32 each), K staged by 16, static shared <=48KB.
#define AS_STR 20
#define BS_STR 132
#define ST_A (128*AS_STR)            // 2560 floats
#define ST_TOTAL (ST_A + 16*BS_STR)  // 4672 floats (18688 B/stage)

template <int SEL>
__global__ void __launch_bounds__(256) gemm_tf32(const float* __restrict__ W,
                                                 const float* __restrict__ bias) {
    const float* __restrict__ A = (SEL == 1) ? g_bufB : g_bufA;
    float* __restrict__ C = (SEL == 0) ? g_bufB : ((SEL == 1) ? g_bufA : g_feat);
    __shared__ float sm[2 * ST_TOTAL];   // 37376 B; reused for epilogue staging
    const uint32_t sb = smem_u32(sm);
    const int tid = threadIdx.x, wid = tid >> 5, lane = tid & 31;
    const int wm = wid >> 2, wn = wid & 3;
    const int m0 = blockIdx.y << 7, n0 = blockIdx.x << 7;

    wmma::fragment<wmma::accumulator, 16, 16, 8, float> acc[4][2];
#pragma unroll
    for (int i = 0; i < 4; i++)
#pragma unroll
        for (int j = 0; j < 2; j++) wmma::fill_fragment(acc[i][j], 0.0f);

    auto load_stage = [&](int s) {
        const uint32_t base = sb + (uint32_t)(s & 1) * (ST_TOTAL * 4);
        const int k0 = s << 4;
#pragma unroll
        for (int i = 0; i < 2; i++) {
            const int f = tid + (i << 8);
            const int m = f >> 2, q = (f & 3) << 2;  // 128 rows x 4 float4
            cp16(base + (uint32_t)(m * AS_STR + q) * 4,
                 A + (size_t)(m0 + m) * 512 + k0 + q);
        }
#pragma unroll
        for (int i = 0; i < 2; i++) {
            const int f = tid + (i << 8);
            const int kk = f >> 5, q = (f & 31) << 2;  // 16 rows x 32 float4
            cp16(base + (uint32_t)(ST_A + kk * BS_STR + q) * 4,
                 W + (size_t)(k0 + kk) * 512 + n0 + q);
        }
        CP_COMMIT();
    };

    load_stage(0);
    for (int s = 0; s < 32; s++) {
        if (s < 31) { load_stage(s + 1); CP_WAIT1(); } else { CP_WAIT0(); }
        __syncthreads();
        const float* As = sm + (s & 1) * ST_TOTAL;
        const float* Bs = As + ST_A;
#pragma unroll
        for (int ks = 0; ks < 2; ks++) {
            wmma::fragment<wmma::matrix_a, 16, 16, 8, wmma::precision::tf32, wmma::row_major> ah[4], al[4];
            wmma::fragment<wmma::matrix_b, 16, 16, 8, wmma::precision::tf32, wmma::row_major> bh[2], bl[2];
#pragma unroll
            for (int i = 0; i < 4; i++) {
                wmma::fragment<wmma::matrix_a, 16, 16, 8, wmma::precision::tf32, wmma::row_major> raw;
                wmma::load_matrix_sync(raw, As + (wm * 64 + i * 16) * AS_STR + ks * 8, AS_STR);
#pragma unroll
                for (int t = 0; t < raw.num_elements; t++) {
                    float v = raw.x[t], h = tf32r(v);
                    ah[i].x[t] = h;
                    al[i].x[t] = tf32r(v - h);
                }
            }
#pragma unroll
            for (int j = 0; j < 2; j++) {
                wmma::fragment<wmma::matrix_b, 16, 16, 8, wmma::precision::tf32, wmma::row_major> raw;
                wmma::load_matrix_sync(raw, Bs + (ks * 8) * BS_STR + wn * 32 + j * 16, BS_STR);
#pragma unroll
                for (int t = 0; t < raw.num_elements; t++) {
                    float v = raw.x[t], h = tf32r(v);
                    bh[j].x[t] = h;
                    bl[j].x[t] = tf32r(v - h);
                }
            }
#pragma unroll
            for (int i = 0; i < 4; i++)
#pragma unroll
                for (int j = 0; j < 2; j++) {
                    wmma::mma_sync(acc[i][j], ah[i], bh[j], acc[i][j]);
                    wmma::mma_sync(acc[i][j], al[i], bh[j], acc[i][j]);
                    wmma::mma_sync(acc[i][j], ah[i], bl[j], acc[i][j]);
                }
        }
        __syncthreads();
    }
    __syncthreads();

    // epilogue: per-warp staging (16x36) aliased into sm
    float* epiW = sm + wid * (16 * 36);
    const int r = lane & 15, cblk = (lane >> 4) << 4;
#pragma unroll
    for (int i = 0; i < 4; i++) {
        wmma::store_matrix_sync(epiW, acc[i][0], 36, wmma::mem_row_major);
        wmma::store_matrix_sync(epiW + 16, acc[i][1], 36, wmma::mem_row_major);
        __syncwarp();
        const int row = m0 + wm * 64 + i * 16 + r;
        const int col = n0 + wn * 32 + cblk;
        const float* erow = epiW + r * 36 + cblk;
        float* dst = C + (size_t)row * 512 + col;
#pragma unroll
        for (int c = 0; c < 16; c += 4) {
            float4 o;
            o.x = erow[c + 0] + __ldg(bias + col + c + 0);
            o.y = erow[c + 1] + __ldg(bias + col + c + 1);
            o.z = erow[c + 2] + __ldg(bias + col + c + 2);
            o.w = erow[c + 3] + __ldg(bias + col + c + 3);
            if (SEL != 2) { o.x = sinf(o.x); o.y = sinf(o.y); o.z = sinf(o.z); o.w = sinf(o.w); }
            *(float4*)(dst + c) = o;
        }
        __syncwarp();
    }
}

// ---------------- 4) cov = F^T F via wmma tf32 3-term (static shared) ----------------
#define CV_STR 136
#define CV_HALF (16*CV_STR)            // 2176 floats
#define CV_TOTAL (2*CV_HALF)           // 4352 floats (17408 B/stage)

__global__ void __launch_bounds__(256) cov_wmma() {
    __shared__ float sm[2 * CV_TOTAL];  // 34816 B
    const uint32_t sb = smem_u32(sm);
    const int tid = threadIdx.x, wid = tid >> 5;
    const int wm = wid >> 2, wn = wid & 3;
    const int b = blockIdx.z;
    const int m0 = blockIdx.y << 7, n0 = blockIdx.x << 7;
    const float* __restrict__ F = g_feat + (size_t)b * NC * 512;

    wmma::fragment<wmma::accumulator, 16, 16, 8, float> acc[4][2];
#pragma unroll
    for (int i = 0; i < 4; i++)
#pragma unroll
        for (int j = 0; j < 2; j++) wmma::fill_fragment(acc[i][j], 0.0f);

    auto load_stage = [&](int s) {
        const uint32_t base = sb + (uint32_t)(s & 1) * (CV_TOTAL * 4);
        const int k0 = s << 4;
#pragma unroll
        for (int i = 0; i < 2; i++) {
            const int f = tid + (i << 8);
            const int kk = f >> 5, q = (f & 31) << 2;
            const uint32_t d = base + (uint32_t)(kk * CV_STR + q) * 4;
            cp16(d, F + (size_t)(k0 + kk) * 512 + m0 + q);
            cp16(d + CV_HALF * 4, F + (size_t)(k0 + kk) * 512 + n0 + q);
        }
        CP_COMMIT();
    };

    load_stage(0);
    for (int s = 0; s < 64; s++) {
        if (s < 63) { load_stage(s + 1); CP_WAIT1(); } else { CP_WAIT0(); }
        __syncthreads();
        const float* Fm = sm + (s & 1) * CV_TOTAL;
        const float* Fn = Fm + CV_HALF;
#pragma unroll
        for (int ks = 0; ks < 2; ks++) {
            wmma::fragment<wmma::matrix_a, 16, 16, 8, wmma::precision::tf32, wmma::col_major> ah[4], al[4];
            wmma::fragment<wmma::matrix_b, 16, 16, 8, wmma::precision::tf32, wmma::row_major> bh[2], bl[2];
#pragma unroll
            for (int i = 0; i < 4; i++) {
                wmma::fragment<wmma::matrix_a, 16, 16, 8, wmma::precision::tf32, wmma::col_major> raw;
                wmma::load_matrix_sync(raw, Fm + (ks * 8) * CV_STR + wm * 64 + i * 16, CV_STR);
#pragma unroll
                for (int t = 0; t < raw.num_elements; t++) {
                    float v = raw.x[t], h = tf32r(v);
                    ah[i].x[t] = h;
                    al[i].x[t] = tf32r(v - h);
                }
            }
#pragma unroll
            for (int j = 0; j < 2; j++) {
                wmma::fragment<wmma::matrix_b, 16, 16, 8, wmma::precision::tf32, wmma::row_major> raw;
                wmma::load_matrix_sync(raw, Fn + (ks * 8) * CV_STR + wn * 32 + j * 16, CV_STR);
#pragma unroll
                for (int t = 0; t < raw.num_elements; t++) {
                    float v = raw.x[t], h = tf32r(v);
                    bh[j].x[t] = h;
                    bl[j].x[t] = tf32r(v - h);
                }
            }
#pragma unroll
            for (int i = 0; i < 4; i++)
#pragma unroll
                for (int j = 0; j < 2; j++) {
                    wmma::mma_sync(acc[i][j], ah[i], bh[j], acc[i][j]);
                    wmma::mma_sync(acc[i][j], al[i], bh[j], acc[i][j]);
                    wmma::mma_sync(acc[i][j], ah[i], bl[j], acc[i][j]);
                }
        }
        __syncthreads();
    }

    float* Cc = g_cov + (size_t)b * COVSTRIDE;
#pragma unroll
    for (int i = 0; i < 4; i++)
#pragma unroll
        for (int j = 0; j < 2; j++)
            wmma::store_matrix_sync(Cc + (size_t)(m0 + wm * 64 + i * 16) * LD + n0 + wn * 32 + j * 16,
                                    acc[i][j], LD, wmma::mem_row_major);
}

// ---------------- 5) xty + cov borders + lambda*I ----------------
__global__ void __launch_bounds__(512) xty_border_kernel(const float* __restrict__ lnv) {
    const int b = blockIdx.x, tid = threadIdx.x;
    __shared__ float yc_s[NC];
    for (int i = tid; i < NC; i += 512) yc_s[i] = g_yc[b * NC + i];
    __syncthreads();
    const float* __restrict__ F = g_feat + (size_t)b * NC * H;
    float s0 = 0.f, s1 = 0.f;
    for (int n = 0; n < NC; n++) {
        float f = F[(size_t)n * H + tid];
        s0 += f;
        s1 += f * yc_s[n];
    }
    const float lam = expf(lnv[0]);
    float* Cc = g_cov + (size_t)b * COVSTRIDE;
    g_xty[b * LD + tid] = s1;
    Cc[512 * LD + tid] = s0;
    Cc[(size_t)tid * LD + 512] = s0;
    Cc[(size_t)tid * LD + tid] += lam;
    if (tid == 0) {
        float sy = 0.f;
        for (int n = 0; n < NC; n++) sy += yc_s[n];
        g_xty[b * LD + 512] = sy;
        Cc[512 * LD + 512] = (float)NC + lam;
    }
}

// ---------------- 6) in-place Cholesky (lower) ----------------
__global__ void __launch_bounds__(1024) cholesky_kernel() {
    const int b = blockIdx.x;
    float* __restrict__ A = g_cov + (size_t)b * COVSTRIDE;
    __shared__ float colk[NRP1];
    __shared__ float sinv;
    const int tid = threadIdx.x;
    const int warp = tid >> 5, lane = tid & 31;
    for (int k = 0; k < NRP1; k++) {
        if (tid == 0) {
            float d = A[(size_t)k * LD + k];
            float sq = sqrtf(d);
            A[(size_t)k * LD + k] = sq;
            sinv = 1.0f / sq;
        }
        __syncthreads();
        const float inv = sinv;
        for (int i = k + 1 + tid; i < NRP1; i += 1024) {
            float v = A[(size_t)i * LD + k] * inv;
            A[(size_t)i * LD + k] = v;
            colk[i] = v;
        }
        __syncthreads();
        for (int i = k + 1 + warp; i < NRP1; i += 32) {
            const float Lik = colk[i];
            for (int j = k + 1 + lane; j <= i; j += 32)
                A[(size_t)i * LD + j] -= Lik * colk[j];
        }
        __syncthreads();
    }
}

// ---------------- 7) triangular solves ----------------
__global__ void __launch_bounds__(512) solve_kernel() {
    const int b = blockIdx.x, tid = threadIdx.x;
    const float* __restrict__ L = g_cov + (size_t)b * COVSTRIDE;
    __shared__ float vs[NRP1];
    __shared__ float invd[NRP1];
    for (int i = tid; i < NRP1; i += 512) {
        vs[i] = g_xty[b * LD + i];
        invd[i] = 1.0f / L[(size_t)i * LD + i];
    }
    __syncthreads();
    for (int k = 0; k < NRP1; k++) {
        if (tid == 0) vs[k] *= invd[k];
        __syncthreads();
        const float vk = vs[k];
        for (int i = k + 1 + tid; i < NRP1; i += 512)
            vs[i] -= L[(size_t)i * LD + k] * vk;
        __syncthreads();
    }
    for (int k = NRP1 - 1; k >= 0; k--) {
        if (tid == 0) vs[k] *= invd[k];
        __syncthreads();
        const float wk = vs[k];
        for (int j = tid; j < k; j += 512)
            vs[j] -= L[(size_t)k * LD + j] * wk;
        __syncthreads();
    }
    for (int i = tid; i < NRP1; i += 512) g_xty[b * LD + i] = vs[i];
}

// ---------------- 8) predict ----------------
__global__ void __launch_bounds__(256) predict_kernel(float* __restrict__ out) {
    const int g = (blockIdx.x * 256 + threadIdx.x) >> 5;
    const int lane = threadIdx.x & 31;
    const int b = g >> 10;
    const float* __restrict__ tr = g_feat + (size_t)(NCTX + g) * H;
    const float* __restrict__ w = g_xty + b * LD;
    float acc = 0.f;
#pragma unroll
    for (int t = lane; t < H; t += 32) acc = fmaf(tr[t], w[t], acc);
#pragma unroll
    for (int o = 16; o; o >>= 1) acc += __shfl_xor_sync(0xffffffffu, acc, o);
    if (lane == 0) out[g] = fmaf(acc + w[H], g_std[b], g_mean[b]);
}

// ---------------- launch (only harness pointers cross host->device) ----------------
extern "C" void kernel_launch(void* const* d_in, const int* in_sizes, int n_in,
                              void* d_out, int out_size) {
    const float* x_ctx = (const float*)d_in[0];
    const float* y_ctx = (const float*)d_in[1];
    const float* x_tgt = (const float*)d_in[2];
    const float* W0 = (const float*)d_in[3];
    const float* b0 = (const float*)d_in[4];
    const float* W1 = (const float*)d_in[5];
    const float* b1 = (const float*)d_in[6];
    const float* W2 = (const float*)d_in[7];
    const float* b2 = (const float*)d_in[8];
    const float* Wr = (const float*)d_in[9];
    const float* br = (const float*)d_in[10];
    const float* lnv = (const float*)d_in[11];
    float* out = (float*)d_out;

    stats_kernel<<<BATCH, 256>>>(y_ctx);
    layer0_kernel<<<(NP * (H / 4)) / 256, 256>>>(x_ctx, x_tgt, W0, b0);   // -> g_bufA

    gemm_tf32<0><<<dim3(4, NP / 128), 256>>>(W1, b1);   // g_bufA -> g_bufB (sin)
    gemm_tf32<1><<<dim3(4, NP / 128), 256>>>(W2, b2);   // g_bufB -> g_bufA (sin)
    gemm_tf32<2><<<dim3(4, NP / 128), 256>>>(Wr, br);   // g_bufA -> g_feat (linear)

    cov_wmma<<<dim3(4, 4, BATCH), 256>>>();
    xty_border_kernel<<<BATCH, 512>>>(lnv);
    cholesky_kernel<<<BATCH, 1024>>>();
    solve_kernel<<<BATCH, 512>>>();
    predict_kernel<<<8192, 256>>>(out);
}

// round 9
// speedup vs baseline: 1.3617x; 1.3617x over previous
#include <cuda_runtime.h>
#include <cuda_bf16.h>
#include <mma.h>
#include <cstdint>
#include <math.h>

using namespace nvcuda;

// ---------------- problem constants ----------------
#define BATCH 64
#define NC 1024
#define NT 1024
#define H 512
#define NP (BATCH*(NC+NT))   // 131072 points
#define NCTX (BATCH*NC)      // 65536 context rows
#define NRP1 513
#define LD 520
#define COVSTRIDE (NRP1*LD)
#define OMEGA0 30.0f

// ---------------- scratch (static device globals; referenced ONLY in device code) ----------------
__device__ __nv_bfloat16 g_X1h[(size_t)NP * H];
__device__ __nv_bfloat16 g_X1l[(size_t)NP * H];
__device__ __nv_bfloat16 g_X2h[(size_t)NP * H];
__device__ __nv_bfloat16 g_X2l[(size_t)NP * H];
__device__ __nv_bfloat16 g_Wh[3 * H * H];
__device__ __nv_bfloat16 g_Wl[3 * H * H];
__device__ float g_feat[(size_t)NP * H];
__device__ float g_cov[(size_t)BATCH * COVSTRIDE];
__device__ float g_xty[BATCH * LD];
__device__ float g_yc[BATCH * NC];
__device__ float g_mean[BATCH];
__device__ float g_std[BATCH];

// ---------------- helpers ----------------
__device__ __forceinline__ uint32_t smem_u32(const void* p) {
    uint32_t a;
    asm("{ .reg .u64 t; cvta.to.shared.u64 t, %1; cvt.u32.u64 %0, t; }" : "=r"(a) : "l"(p));
    return a;
}
__device__ __forceinline__ void cp16(uint32_t dst, const void* src) {
    asm volatile("cp.async.cg.shared.global [%0], [%1], 16;" :: "r"(dst), "l"(src));
}
#define CP_COMMIT() asm volatile("cp.async.commit_group;" ::: "memory")
#define CP_WAIT1()  asm volatile("cp.async.wait_group 1;" ::: "memory")
#define CP_WAIT0()  asm volatile("cp.async.wait_group 0;" ::: "memory")

__device__ __forceinline__ float tf32r(float v) {
    uint32_t u;
    asm("cvt.rna.tf32.f32 %0, %1;" : "=r"(u) : "f"(v));
    return __uint_as_float(u);
}
__device__ __forceinline__ void bsplit(float v, __nv_bfloat16& h, __nv_bfloat16& l) {
    h = __float2bfloat16_rn(v);
    l = __float2bfloat16_rn(v - __bfloat162float(h));
}

// ---------------- 0) weight split: W[k][n] fp32 -> bf16 hi/lo (same layout) ----------------
__global__ void __launch_bounds__(256) wprep_kernel(const float* __restrict__ W1,
                                                    const float* __restrict__ W2,
                                                    const float* __restrict__ Wr) {
    const int id = blockIdx.x * 256 + threadIdx.x;   // [0, 262144)
    const int l = blockIdx.y;
    const float* W = (l == 0) ? W1 : ((l == 1) ? W2 : Wr);
    __nv_bfloat16 h, lo;
    bsplit(W[id], h, lo);
    g_Wh[l * 262144 + id] = h;
    g_Wl[l * 262144 + id] = lo;
}

// ---------------- 1) per-batch mean/std (ddof=1) + normalize ----------------
__global__ void __launch_bounds__(256) stats_kernel(const float* __restrict__ y) {
    const int b = blockIdx.x, tid = threadIdx.x;
    __shared__ float red[256];
    float v[4];
#pragma unroll
    for (int t = 0; t < 4; t++) v[t] = y[b * NC + tid + t * 256];
    red[tid] = v[0] + v[1] + v[2] + v[3]; __syncthreads();
    for (int st = 128; st > 0; st >>= 1) { if (tid < st) red[tid] += red[tid + st]; __syncthreads(); }
    const float mean = red[0] * (1.0f / NC);
    __syncthreads();
    float q = 0.f;
#pragma unroll
    for (int t = 0; t < 4; t++) { float d = v[t] - mean; q += d * d; }
    red[tid] = q; __syncthreads();
    for (int st = 128; st > 0; st >>= 1) { if (tid < st) red[tid] += red[tid + st]; __syncthreads(); }
    const float sd = sqrtf(red[0] * (1.0f / (NC - 1)));
    const float inv = 1.0f / sd;
#pragma unroll
    for (int t = 0; t < 4; t++) g_yc[b * NC + tid + t * 256] = (v[t] - mean) * inv;
    if (tid == 0) { g_mean[b] = mean; g_std[b] = sd; }
}

// ---------------- 2) SIREN layer 0 (XD=1) -> bf16 hi/lo ----------------
__global__ void __launch_bounds__(256) layer0_kernel(const float* __restrict__ xc,
                                                     const float* __restrict__ xt,
                                                     const float* __restrict__ W0,
                                                     const float* __restrict__ b0) {
    const int idx = blockIdx.x * 256 + threadIdx.x;
    const int p = idx >> 7;
    const int j4 = (idx & 127) << 2;
    const float x = (p < NCTX) ? xc[p] : xt[p - NCTX];
    const float4 w = *(const float4*)(W0 + j4);
    const float4 bb = *(const float4*)(b0 + j4);
    float v[4];
    v[0] = sinf(OMEGA0 * fmaf(x, w.x, bb.x));
    v[1] = sinf(OMEGA0 * fmaf(x, w.y, bb.y));
    v[2] = sinf(OMEGA0 * fmaf(x, w.z, bb.z));
    v[3] = sinf(OMEGA0 * fmaf(x, w.w, bb.w));
    __nv_bfloat162 hh[2], ll[2];
#pragma unroll
    for (int t = 0; t < 2; t++) {
        __nv_bfloat16 h0, l0, h1, l1;
        bsplit(v[2 * t], h0, l0);
        bsplit(v[2 * t + 1], h1, l1);
        hh[t] = __nv_bfloat162(h0, h1);
        ll[t] = __nv_bfloat162(l0, l1);
    }
    const size_t base = (size_t)p * H + j4;
    *(__nv_bfloat162*)(g_X1h + base) = hh[0];
    *(__nv_bfloat162*)(g_X1h + base + 2) = hh[1];
    *(__nv_bfloat162*)(g_X1l + base) = ll[0];
    *(__nv_bfloat162*)(g_X1l + base + 2) = ll[1];
}

// ---------------- 3) bf16 3-term wmma GEMM: C = act(A @ W + b), pre-split operands ----------------
// SEL 0: X1 -> X2 (sin, split).  SEL 1: X2 -> X1 (sin, split).  SEL 2: X1 -> g_feat (linear fp32).
// CTA 128x128, 8 warps (64x32), K staged by 16, double-buffered, static shared.
#define BA_STR 24
#define BB_STR 136
#define BO_AL 3072
#define BO_BH 6144
#define BO_BL 8320
#define BSTG  10496   // bf16 elements per stage

template <int SEL>
__global__ void __launch_bounds__(256) gemm_bf16(const float* __restrict__ bias) {
    const __nv_bfloat16* __restrict__ Ah = (SEL == 1) ? g_X2h : g_X1h;
    const __nv_bfloat16* __restrict__ Al = (SEL == 1) ? g_X2l : g_X1l;
    const __nv_bfloat16* __restrict__ Wh = g_Wh + SEL * 262144;
    const __nv_bfloat16* __restrict__ Wl = g_Wl + SEL * 262144;

    __shared__ __nv_bfloat16 sm[2 * BSTG];   // 41984 B; fp32 epilogue staging aliases in
    const uint32_t sb = smem_u32(sm);
    const int tid = threadIdx.x, wid = tid >> 5, lane = tid & 31;
    const int wm = wid >> 2, wn = wid & 3;
    const int m0 = blockIdx.y << 7, n0 = blockIdx.x << 7;

    wmma::fragment<wmma::accumulator, 16, 16, 16, float> acc[4][2];
#pragma unroll
    for (int i = 0; i < 4; i++)
#pragma unroll
        for (int j = 0; j < 2; j++) wmma::fill_fragment(acc[i][j], 0.0f);

    auto load_stage = [&](int s) {
        const uint32_t base = sb + (uint32_t)(s & 1) * (BSTG * 2);
        const int k0 = s << 4;
        {   // A: 128 rows x 2 chunks of 8 bf16 (hi and lo)
            const int m = tid >> 1, q = tid & 1;
            const uint32_t d = base + (uint32_t)(m * BA_STR + (q << 3)) * 2;
            const size_t src = (size_t)(m0 + m) * H + k0 + (q << 3);
            cp16(d, Ah + src);
            cp16(d + BO_AL * 2, Al + src);
        }
        {   // B: 16 k-rows x 16 chunks of 8 bf16 (hi and lo)
            const int kk = tid >> 4, q = tid & 15;
            const uint32_t d = base + (uint32_t)(BO_BH + kk * BB_STR + (q << 3)) * 2;
            const size_t src = (size_t)(k0 + kk) * H + n0 + (q << 3);
            cp16(d, Wh + src);
            cp16(d + (BO_BL - BO_BH) * 2, Wl + src);
        }
        CP_COMMIT();
    };

    load_stage(0);
    for (int s = 0; s < 32; s++) {
        if (s < 31) { load_stage(s + 1); CP_WAIT1(); } else { CP_WAIT0(); }
        __syncthreads();
        const __nv_bfloat16* As_h = sm + (s & 1) * BSTG;
        const __nv_bfloat16* As_l = As_h + BO_AL;
        const __nv_bfloat16* Bs_h = As_h + BO_BH;
        const __nv_bfloat16* Bs_l = As_h + BO_BL;

        wmma::fragment<wmma::matrix_a, 16, 16, 16, __nv_bfloat16, wmma::row_major> ah[4], al[4];
        wmma::fragment<wmma::matrix_b, 16, 16, 16, __nv_bfloat16, wmma::row_major> bh[2], bl[2];
#pragma unroll
        for (int i = 0; i < 4; i++) {
            const int ro = (wm * 64 + i * 16) * BA_STR;
            wmma::load_matrix_sync(ah[i], As_h + ro, BA_STR);
            wmma::load_matrix_sync(al[i], As_l + ro, BA_STR);
        }
#pragma unroll
        for (int j = 0; j < 2; j++) {
            const int bo = wn * 32 + j * 16;
            wmma::load_matrix_sync(bh[j], Bs_h + bo, BB_STR);
            wmma::load_matrix_sync(bl[j], Bs_l + bo, BB_STR);
        }
#pragma unroll
        for (int i = 0; i < 4; i++)
#pragma unroll
            for (int j = 0; j < 2; j++) {
                wmma::mma_sync(acc[i][j], ah[i], bh[j], acc[i][j]);
                wmma::mma_sync(acc[i][j], al[i], bh[j], acc[i][j]);
                wmma::mma_sync(acc[i][j], ah[i], bl[j], acc[i][j]);
            }
        __syncthreads();
    }
    __syncthreads();

    // epilogue: per-warp fp32 staging (16x36) aliased into sm
    float* epiW = (float*)sm + wid * (16 * 36);
    const int r = lane & 15, cblk = (lane >> 4) << 4;
#pragma unroll
    for (int i = 0; i < 4; i++) {
        wmma::store_matrix_sync(epiW, acc[i][0], 36, wmma::mem_row_major);
        wmma::store_matrix_sync(epiW + 16, acc[i][1], 36, wmma::mem_row_major);
        __syncwarp();
        const int row = m0 + wm * 64 + i * 16 + r;
        const int col = n0 + wn * 32 + cblk;
        const float* erow = epiW + r * 36 + cblk;
        if (SEL == 2) {
            float* dst = g_feat + (size_t)row * H + col;
#pragma unroll
            for (int c = 0; c < 16; c += 4) {
                float4 o;
                o.x = erow[c + 0] + __ldg(bias + col + c + 0);
                o.y = erow[c + 1] + __ldg(bias + col + c + 1);
                o.z = erow[c + 2] + __ldg(bias + col + c + 2);
                o.w = erow[c + 3] + __ldg(bias + col + c + 3);
                *(float4*)(dst + c) = o;
            }
        } else {
            __nv_bfloat16* dh = ((SEL == 0) ? g_X2h : g_X1h) + (size_t)row * H + col;
            __nv_bfloat16* dl = ((SEL == 0) ? g_X2l : g_X1l) + (size_t)row * H + col;
#pragma unroll
            for (int c = 0; c < 16; c += 2) {
                float v0 = sinf(erow[c] + __ldg(bias + col + c));
                float v1 = sinf(erow[c + 1] + __ldg(bias + col + c + 1));
                __nv_bfloat16 h0, l0, h1, l1;
                bsplit(v0, h0, l0);
                bsplit(v1, h1, l1);
                *(__nv_bfloat162*)(dh + c) = __nv_bfloat162(h0, h1);
                *(__nv_bfloat162*)(dl + c) = __nv_bfloat162(l0, l1);
            }
        }
        __syncwarp();
    }
}

// ---------------- 4) cov = F^T F via wmma tf32 3-term (static shared) ----------------
#define CV_STR 136
#define CV_HALF (16*CV_STR)            // 2176 floats
#define CV_TOTAL (2*CV_HALF)           // 4352 floats (17408 B/stage)

__global__ void __launch_bounds__(256) cov_wmma() {
    __shared__ float sm[2 * CV_TOTAL];  // 34816 B
    const uint32_t sb = smem_u32(sm);
    const int tid = threadIdx.x, wid = tid >> 5;
    const int wm = wid >> 2, wn = wid & 3;
    const int b = blockIdx.z;
    const int m0 = blockIdx.y << 7, n0 = blockIdx.x << 7;
    const float* __restrict__ F = g_feat + (size_t)b * NC * H;

    wmma::fragment<wmma::accumulator, 16, 16, 8, float> acc[4][2];
#pragma unroll
    for (int i = 0; i < 4; i++)
#pragma unroll
        for (int j = 0; j < 2; j++) wmma::fill_fragment(acc[i][j], 0.0f);

    auto load_stage = [&](int s) {
        const uint32_t base = sb + (uint32_t)(s & 1) * (CV_TOTAL * 4);
        const int k0 = s << 4;
#pragma unroll
        for (int i = 0; i < 2; i++) {
            const int f = tid + (i << 8);
            const int kk = f >> 5, q = (f & 31) << 2;
            const uint32_t d = base + (uint32_t)(kk * CV_STR + q) * 4;
            cp16(d, F + (size_t)(k0 + kk) * H + m0 + q);
            cp16(d + CV_HALF * 4, F + (size_t)(k0 + kk) * H + n0 + q);
        }
        CP_COMMIT();
    };

    load_stage(0);
    for (int s = 0; s < 64; s++) {
        if (s < 63) { load_stage(s + 1); CP_WAIT1(); } else { CP_WAIT0(); }
        __syncthreads();
        const float* Fm = sm + (s & 1) * CV_TOTAL;
        const float* Fn = Fm + CV_HALF;
#pragma unroll
        for (int ks = 0; ks < 2; ks++) {
            wmma::fragment<wmma::matrix_a, 16, 16, 8, wmma::precision::tf32, wmma::col_major> ah[4], al[4];
            wmma::fragment<wmma::matrix_b, 16, 16, 8, wmma::precision::tf32, wmma::row_major> bh[2], bl[2];
#pragma unroll
            for (int i = 0; i < 4; i++) {
                wmma::fragment<wmma::matrix_a, 16, 16, 8, wmma::precision::tf32, wmma::col_major> raw;
                wmma::load_matrix_sync(raw, Fm + (ks * 8) * CV_STR + wm * 64 + i * 16, CV_STR);
#pragma unroll
                for (int t = 0; t < raw.num_elements; t++) {
                    float v = raw.x[t], h = tf32r(v);
                    ah[i].x[t] = h;
                    al[i].x[t] = tf32r(v - h);
                }
            }
#pragma unroll
            for (int j = 0; j < 2; j++) {
                wmma::fragment<wmma::matrix_b, 16, 16, 8, wmma::precision::tf32, wmma::row_major> raw;
                wmma::load_matrix_sync(raw, Fn + (ks * 8) * CV_STR + wn * 32 + j * 16, CV_STR);
#pragma unroll
                for (int t = 0; t < raw.num_elements; t++) {
                    float v = raw.x[t], h = tf32r(v);
                    bh[j].x[t] = h;
                    bl[j].x[t] = tf32r(v - h);
                }
            }
#pragma unroll
            for (int i = 0; i < 4; i++)
#pragma unroll
                for (int j = 0; j < 2; j++) {
                    wmma::mma_sync(acc[i][j], ah[i], bh[j], acc[i][j]);
                    wmma::mma_sync(acc[i][j], al[i], bh[j], acc[i][j]);
                    wmma::mma_sync(acc[i][j], ah[i], bl[j], acc[i][j]);
                }
        }
        __syncthreads();
    }

    float* Cc = g_cov + (size_t)b * COVSTRIDE;
#pragma unroll
    for (int i = 0; i < 4; i++)
#pragma unroll
        for (int j = 0; j < 2; j++)
            wmma::store_matrix_sync(Cc + (size_t)(m0 + wm * 64 + i * 16) * LD + n0 + wn * 32 + j * 16,
                                    acc[i][j], LD, wmma::mem_row_major);
}

// ---------------- 5) xty + cov borders + lambda*I ----------------
__global__ void __launch_bounds__(512) xty_border_kernel(const float* __restrict__ lnv) {
    const int b = blockIdx.x, tid = threadIdx.x;
    __shared__ float yc_s[NC];
    for (int i = tid; i < NC; i += 512) yc_s[i] = g_yc[b * NC + i];
    __syncthreads();
    const float* __restrict__ F = g_feat + (size_t)b * NC * H;
    float s0 = 0.f, s1 = 0.f;
    for (int n = 0; n < NC; n++) {
        float f = F[(size_t)n * H + tid];
        s0 += f;
        s1 += f * yc_s[n];
    }
    const float lam = expf(lnv[0]);
    float* Cc = g_cov + (size_t)b * COVSTRIDE;
    g_xty[b * LD + tid] = s1;
    Cc[512 * LD + tid] = s0;
    Cc[(size_t)tid * LD + 512] = s0;
    Cc[(size_t)tid * LD + tid] += lam;
    if (tid == 0) {
        float sy = 0.f;
        for (int n = 0; n < NC; n++) sy += yc_s[n];
        g_xty[b * LD + 512] = sy;
        Cc[512 * LD + 512] = (float)NC + lam;
    }
}

// ---------------- 6) in-place Cholesky (lower) ----------------
__global__ void __launch_bounds__(1024) cholesky_kernel() {
    const int b = blockIdx.x;
    float* __restrict__ A = g_cov + (size_t)b * COVSTRIDE;
    __shared__ float colk[NRP1];
    __shared__ float sinv;
    const int tid = threadIdx.x;
    const int warp = tid >> 5, lane = tid & 31;
    for (int k = 0; k < NRP1; k++) {
        if (tid == 0) {
            float d = A[(size_t)k * LD + k];
            float sq = sqrtf(d);
            A[(size_t)k * LD + k] = sq;
            sinv = 1.0f / sq;
        }
        __syncthreads();
        const float inv = sinv;
        for (int i = k + 1 + tid; i < NRP1; i += 1024) {
            float v = A[(size_t)i * LD + k] * inv;
            A[(size_t)i * LD + k] = v;
            colk[i] = v;
        }
        __syncthreads();
        for (int i = k + 1 + warp; i < NRP1; i += 32) {
            const float Lik = colk[i];
            for (int j = k + 1 + lane; j <= i; j += 32)
                A[(size_t)i * LD + j] -= Lik * colk[j];
        }
        __syncthreads();
    }
}

// ---------------- 7) triangular solves ----------------
__global__ void __launch_bounds__(512) solve_kernel() {
    const int b = blockIdx.x, tid = threadIdx.x;
    const float* __restrict__ L = g_cov + (size_t)b * COVSTRIDE;
    __shared__ float vs[NRP1];
    __shared__ float invd[NRP1];
    for (int i = tid; i < NRP1; i += 512) {
        vs[i] = g_xty[b * LD + i];
        invd[i] = 1.0f / L[(size_t)i * LD + i];
    }
    __syncthreads();
    for (int k = 0; k < NRP1; k++) {
        if (tid == 0) vs[k] *= invd[k];
        __syncthreads();
        const float vk = vs[k];
        for (int i = k + 1 + tid; i < NRP1; i += 512)
            vs[i] -= L[(size_t)i * LD + k] * vk;
        __syncthreads();
    }
    for (int k = NRP1 - 1; k >= 0; k--) {
        if (tid == 0) vs[k] *= invd[k];
        __syncthreads();
        const float wk = vs[k];
        for (int j = tid; j < k; j += 512)
            vs[j] -= L[(size_t)k * LD + j] * wk;
        __syncthreads();
    }
    for (int i = tid; i < NRP1; i += 512) g_xty[b * LD + i] = vs[i];
}

// ---------------- 8) predict ----------------
__global__ void __launch_bounds__(256) predict_kernel(float* __restrict__ out) {
    const int g = (blockIdx.x * 256 + threadIdx.x) >> 5;
    const int lane = threadIdx.x & 31;
    const int b = g >> 10;
    const float* __restrict__ tr = g_feat + (size_t)(NCTX + g) * H;
    const float* __restrict__ w = g_xty + b * LD;
    float acc = 0.f;
#pragma unroll
    for (int t = lane; t < H; t += 32) acc = fmaf(tr[t], w[t], acc);
#pragma unroll
    for (int o = 16; o; o >>= 1) acc += __shfl_xor_sync(0xffffffffu, acc, o);
    if (lane == 0) out[g] = fmaf(acc + w[H], g_std[b], g_mean[b]);
}

// ---------------- launch (only harness pointers cross host->device) ----------------
extern "C" void kernel_launch(void* const* d_in, const int* in_sizes, int n_in,
                              void* d_out, int out_size) {
    const float* x_ctx = (const float*)d_in[0];
    const float* y_ctx = (const float*)d_in[1];
    const float* x_tgt = (const float*)d_in[2];
    const float* W0 = (const float*)d_in[3];
    const float* b0 = (const float*)d_in[4];
    const float* W1 = (const float*)d_in[5];
    const float* b1 = (const float*)d_in[6];
    const float* W2 = (const float*)d_in[7];
    const float* b2 = (const float*)d_in[8];
    const float* Wr = (const float*)d_in[9];
    const float* br = (const float*)d_in[10];
    const float* lnv = (const float*)d_in[11];
    float* out = (float*)d_out;

    wprep_kernel<<<dim3(1024, 3), 256>>>(W1, W2, Wr);
    stats_kernel<<<BATCH, 256>>>(y_ctx);
    layer0_kernel<<<(NP * (H / 4)) / 256, 256>>>(x_ctx, x_tgt, W0, b0);   // -> X1 hi/lo

    gemm_bf16<0><<<dim3(4, NP / 128), 256>>>(b1);   // X1 -> X2 (sin)
    gemm_bf16<1><<<dim3(4, NP / 128), 256>>>(b2);   // X2 -> X1 (sin)
    gemm_bf16<2><<<dim3(4, NP / 128), 256>>>(br);   // X1 -> g_feat (linear)

    cov_wmma<<<dim3(4, 4, BATCH), 256>>>();
    xty_border_kernel<<<BATCH, 512>>>(lnv);
    cholesky_kernel<<<BATCH, 1024>>>();
    solve_kernel<<<BATCH, 512>>>();
    predict_kernel<<<8192, 256>>>(out);
}